// round 10
// baseline (speedup 1.0000x reference)
#include <cuda_runtime.h>
#include <cuda_bf16.h>

// Fixed problem shape: B=2, S=2048, D=2048, W=4.
#define SEQ   2048
#define DIM   2048
#define NT    512
#define TROWS 8
#define EPSV  1e-6f
#define D4    (DIM / 4)          // float4s per row = 512
#define SLOT(n) (((n) + 70) % 7) // window slot for row s0+(n)

typedef unsigned long long u64;

// ---- packed f32x2 helpers (sm_103a FFMA2 path; only reachable via PTX) ----
static __device__ __forceinline__ u64 pk2(float lo, float hi) {
    u64 r; asm("mov.b64 %0, {%1, %2};" : "=l"(r) : "f"(lo), "f"(hi)); return r;
}
static __device__ __forceinline__ void up2(u64 v, float& lo, float& hi) {
    asm("mov.b64 {%0, %1}, %2;" : "=f"(lo), "=f"(hi) : "l"(v));
}
static __device__ __forceinline__ u64 mul2(u64 a, u64 b) {
    u64 r; asm("mul.rn.f32x2 %0, %1, %2;" : "=l"(r) : "l"(a), "l"(b)); return r;
}
static __device__ __forceinline__ u64 fma2(u64 a, u64 b, u64 c) {
    u64 r; asm("fma.rn.f32x2 %0, %1, %2, %3;" : "=l"(r) : "l"(a), "l"(b), "l"(c)); return r;
}

static __device__ __forceinline__ float warp_sum(float v) {
#pragma unroll
    for (int o = 16; o > 0; o >>= 1)
        v += __shfl_xor_sync(0xffffffffu, v, o);
    return v;
}

// tanh via exp, safe for large |y| (e -> 0), accurate to ~1e-6 rel.
static __device__ __forceinline__ float fast_tanh(float y) {
    const float e = __expf(-2.0f * fabsf(y));
    const float r = __fdividef(1.0f - e, 1.0f + e);
    return copysignf(r, y);
}

// Thread tid owns d = 4*tid .. 4*tid+3, held as two f32x2 pairs.
__global__ __launch_bounds__(NT, 2)
void gated_kernel(const float4* __restrict__ x4,
                  const float4* __restrict__ w4,     // w4[d] = {w[d][0..3]}
                  const float*  __restrict__ alpha,  // (3,)
                  const float4* __restrict__ rmsw4,  // (D/4,)
                  float4*       __restrict__ out4)
{
    const int tid  = threadIdx.x;
    const int s0   = blockIdx.x * TROWS;
    const int b    = blockIdx.y;
    const int lane = tid & 31;
    const int wid  = tid >> 5;

    const long base = ((long)b * SEQ) * D4 + tid;   // float4 index of (b, s=0, 4*tid)

    // W2[k][pair] = w[d][k]^2 packed as (j0,j1),(j2,j3)
    float4 wq[4];
#pragma unroll
    for (int j = 0; j < 4; j++) wq[j] = __ldg(&w4[4 * tid + j]);
    u64 W2p[4][2];
    {
        const float wkj[4][4] = {
            {wq[0].x, wq[1].x, wq[2].x, wq[3].x},
            {wq[0].y, wq[1].y, wq[2].y, wq[3].y},
            {wq[0].z, wq[1].z, wq[2].z, wq[3].z},
            {wq[0].w, wq[1].w, wq[2].w, wq[3].w}};
#pragma unroll
        for (int k = 0; k < 4; k++) {
            W2p[k][0] = pk2(wkj[k][0] * wkj[k][0], wkj[k][1] * wkj[k][1]);
            W2p[k][1] = pk2(wkj[k][2] * wkj[k][2], wkj[k][3] * wkj[k][3]);
        }
    }
    const float4 rq = __ldg(&rmsw4[tid]);
    const u64 rp[2] = {pk2(rq.x, rq.y), pk2(rq.z, rq.w)};

    // Rolling 7-slot window: row s0+n lives in slot SLOT(n).
    u64 Xp[7][2];
#pragma unroll
    for (int j = 0; j <= 5; j++) {
        const int s  = s0 - j;
        const int sl = SLOT(-j);
        if (s >= 0) {
            const float4 v = x4[base + (long)s * D4];
            Xp[sl][0] = pk2(v.x, v.y); Xp[sl][1] = pk2(v.z, v.w);
        } else {
            Xp[sl][0] = 0ull; Xp[sl][1] = 0ull;
        }
    }
    Xp[SLOT(-6)][0] = 0ull; Xp[SLOT(-6)][1] = 0ull;

    __shared__ float red[2][64][9];   // [buf][partial 0..63][value 0..6], pad 9
    __shared__ float rsb[2][4];       // rsqrt(var_k/D + eps)
    __shared__ float lmb[2][4];       // tanh gates (index 0 unused)

#pragma unroll
    for (int t = 0; t < TROWS; t++) {
        const int buf = t & 1;

        // prefetch row s0+t+1
        u64 in0 = 0ull, in1 = 0ull;
        if (t < TROWS - 1) {
            const float4 v = x4[base + (long)(s0 + t + 1) * D4];
            in0 = pk2(v.x, v.y); in1 = pk2(v.z, v.w);
        }

        // ---- stage 1: partials for row t ----
        const int a0 = SLOT(t),     a1 = SLOT(t - 1), a2 = SLOT(t - 2);
        const int a3 = SLOT(t - 3), a4 = SLOT(t - 4), a5 = SLOT(t - 5);

        u64 vd0 = 0ull, vd1 = 0ull, vd2 = 0ull;
        u64 vv0 = 0ull, vv1 = 0ull, vv2 = 0ull, vv3 = 0ull;
#pragma unroll
        for (int p = 0; p < 2; p++) {
            const u64 x0 = Xp[a0][p], x1 = Xp[a1][p], x2 = Xp[a2][p];
            const u64 x3 = Xp[a3][p], x4v = Xp[a4][p], x5 = Xp[a5][p];
            vd0 = fma2(x0, x1, vd0);
            vd1 = fma2(x0, x2, vd1);
            vd2 = fma2(x0, x3, vd2);
            const u64 q0 = mul2(x0, x2);
            const u64 q1 = mul2(x1, x3);
            const u64 q2 = mul2(x2, x4v);
            const u64 q3 = mul2(x3, x5);
            vv0 = fma2(mul2(q0, q0), W2p[0][p], vv0);
            vv1 = fma2(mul2(q1, q1), W2p[1][p], vv1);
            vv2 = fma2(mul2(q2, q2), W2p[2][p], vv2);
            vv3 = fma2(mul2(q3, q3), W2p[3][p], vv3);
        }
        float vals[7];
        {
            float lo, hi;
            up2(vd0, lo, hi); vals[0] = lo + hi;
            up2(vd1, lo, hi); vals[1] = lo + hi;
            up2(vd2, lo, hi); vals[2] = lo + hi;
            up2(vv0, lo, hi); vals[3] = lo + hi;
            up2(vv1, lo, hi); vals[4] = lo + hi;
            up2(vv2, lo, hi); vals[5] = lo + hi;
            up2(vv3, lo, hi); vals[6] = lo + hi;
        }
        // 3-level butterfly: lane L ends with sum over lanes == L (mod 4)
#pragma unroll
        for (int i = 0; i < 7; i++) {
            vals[i] += __shfl_xor_sync(0xffffffffu, vals[i], 16);
            vals[i] += __shfl_xor_sync(0xffffffffu, vals[i], 8);
            vals[i] += __shfl_xor_sync(0xffffffffu, vals[i], 4);
        }
        if (lane < 4) {
            const int p = (wid << 2) | lane;
#pragma unroll
            for (int i = 0; i < 7; i++) red[buf][p][i] = vals[i];
        }
        __syncthreads();

        // ---- stage 2 (warps 0..6): scales for row t, overlapped with recombine below ----
        if (wid == 0) {
            const float v = warp_sum(red[buf][lane][3] + red[buf][lane + 32][3]);
            if (lane == 0) rsb[buf][0] = rsqrtf(v * (1.0f / DIM) + EPSV);
        } else if (wid <= 3) {
            const int k = wid;
            const float v = warp_sum(red[buf][lane][3 + k] + red[buf][lane + 32][3 + k]);
            if (lane == 0) rsb[buf][k] = rsqrtf(v * (1.0f / DIM) + EPSV);
        } else if (wid <= 6) {
            const int k = wid - 3;
            const float v = warp_sum(red[buf][lane][k - 1] + red[buf][lane + 32][k - 1]);
            if (lane == 0) lmb[buf][k] = fast_tanh(v * __ldg(&alpha[k - 1]));
        }

        // ---- recombine row t-1 with previous iteration's scales ----
        if (t >= 1) {
            const int pb = (t - 1) & 1;
            const float cs0 = rsb[pb][0];
            const float cs1 = lmb[pb][1] * rsb[pb][1];
            const float cs2 = lmb[pb][2] * rsb[pb][2];
            const float cs3 = lmb[pb][3] * rsb[pb][3];
            const u64 cp0 = pk2(cs0, cs0), cp1 = pk2(cs1, cs1);
            const u64 cp2 = pk2(cs2, cs2), cp3 = pk2(cs3, cs3);
            const int b0 = SLOT(t - 1), b1 = SLOT(t - 2), b2 = SLOT(t - 3);
            const int b3 = SLOT(t - 4), b4 = SLOT(t - 5), b5 = SLOT(t - 6);
            float oo[4];
#pragma unroll
            for (int p = 0; p < 2; p++) {
                const u64 x0 = Xp[b0][p];
                const u64 q0 = mul2(x0, Xp[b2][p]);
                const u64 q1 = mul2(Xp[b1][p], Xp[b3][p]);
                const u64 q2 = mul2(Xp[b2][p], Xp[b4][p]);
                const u64 q3 = mul2(Xp[b3][p], Xp[b5][p]);
                u64 acc = mul2(cp0, mul2(q0, W2p[0][p]));
                acc = fma2(cp1, mul2(q1, W2p[1][p]), acc);
                acc = fma2(cp2, mul2(q2, W2p[2][p]), acc);
                acc = fma2(cp3, mul2(q3, W2p[3][p]), acc);
                const u64 o = fma2(rp[p], acc, x0);
                up2(o, oo[2 * p], oo[2 * p + 1]);
            }
            float4 ov; ov.x = oo[0]; ov.y = oo[1]; ov.z = oo[2]; ov.w = oo[3];
            out4[base + (long)(s0 + t - 1) * D4] = ov;
        }

        // commit prefetched row into its slot (after recombine consumed row t-6)
        if (t < TROWS - 1) {
            Xp[SLOT(t + 1)][0] = in0;
            Xp[SLOT(t + 1)][1] = in1;
        }
    }

    // ---- epilogue: recombine last row (t = TROWS-1) ----
    __syncthreads();
    {
        const int t  = TROWS;            // "virtual" iteration
        const int pb = (t - 1) & 1;
        const float cs0 = rsb[pb][0];
        const float cs1 = lmb[pb][1] * rsb[pb][1];
        const float cs2 = lmb[pb][2] * rsb[pb][2];
        const float cs3 = lmb[pb][3] * rsb[pb][3];
        const u64 cp0 = pk2(cs0, cs0), cp1 = pk2(cs1, cs1);
        const u64 cp2 = pk2(cs2, cs2), cp3 = pk2(cs3, cs3);
        const int b0 = SLOT(t - 1), b1 = SLOT(t - 2), b2 = SLOT(t - 3);
        const int b3 = SLOT(t - 4), b4 = SLOT(t - 5), b5 = SLOT(t - 6);
        float oo[4];
#pragma unroll
        for (int p = 0; p < 2; p++) {
            const u64 x0 = Xp[b0][p];
            const u64 q0 = mul2(x0, Xp[b2][p]);
            const u64 q1 = mul2(Xp[b1][p], Xp[b3][p]);
            const u64 q2 = mul2(Xp[b2][p], Xp[b4][p]);
            const u64 q3 = mul2(Xp[b3][p], Xp[b5][p]);
            u64 acc = mul2(cp0, mul2(q0, W2p[0][p]));
            acc = fma2(cp1, mul2(q1, W2p[1][p]), acc);
            acc = fma2(cp2, mul2(q2, W2p[2][p]), acc);
            acc = fma2(cp3, mul2(q3, W2p[3][p]), acc);
            const u64 o = fma2(rp[p], acc, x0);
            up2(o, oo[2 * p], oo[2 * p + 1]);
        }
        float4 ov; ov.x = oo[0]; ov.y = oo[1]; ov.z = oo[2]; ov.w = oo[3];
        out4[base + (long)(s0 + t - 1) * D4] = ov;
    }
}

extern "C" void kernel_launch(void* const* d_in, const int* in_sizes, int n_in,
                              void* d_out, int out_size)
{
    const float* x     = (const float*)d_in[0];
    const float* w     = (const float*)d_in[1];
    const float* alpha = (const float*)d_in[2];
    const float* rmsw  = (const float*)d_in[3];
    float* out = (float*)d_out;

    const long total = (long)in_sizes[0];
    const int  B     = (int)(total / ((long)SEQ * DIM));   // = 2

    dim3 grid(SEQ / TROWS, B);
    gated_kernel<<<grid, NT>>>((const float4*)x, (const float4*)w, alpha,
                               (const float4*)rmsw, (float4*)out);
}

// round 11
// speedup vs baseline: 1.1351x; 1.1351x over previous
#include <cuda_runtime.h>
#include <cuda_bf16.h>

// Fixed problem shape: B=2, S=2048, D=2048, W=4.
#define SEQ   2048
#define DIM   2048
#define NT    512
#define TR1   16                  // rows per CTA, kernel 1
#define TR3   16                  // rows per CTA, kernel 3
#define EPSV  1e-6f
#define D4    (DIM / 4)           // float4s per row = 512
#define SLOT6(n) (((n) + 60) % 6) // 6-slot rolling window

typedef unsigned long long u64;

// Scratch (device globals — no allocation). [b][s][val(7 pad 8)][warp]
__device__ float  g_part[2][SEQ][8][16];
__device__ float4 g_scale[2][SEQ];

// ---- packed f32x2 helpers ----
static __device__ __forceinline__ u64 pk2(float lo, float hi) {
    u64 r; asm("mov.b64 %0, {%1, %2};" : "=l"(r) : "f"(lo), "f"(hi)); return r;
}
static __device__ __forceinline__ void up2(u64 v, float& lo, float& hi) {
    asm("mov.b64 {%0, %1}, %2;" : "=f"(lo), "=f"(hi) : "l"(v));
}
static __device__ __forceinline__ u64 mul2(u64 a, u64 b) {
    u64 r; asm("mul.rn.f32x2 %0, %1, %2;" : "=l"(r) : "l"(a), "l"(b)); return r;
}
static __device__ __forceinline__ u64 fma2(u64 a, u64 b, u64 c) {
    u64 r; asm("fma.rn.f32x2 %0, %1, %2, %3;" : "=l"(r) : "l"(a), "l"(b), "l"(c)); return r;
}

#define WSUM(v) do { \
    v += __shfl_xor_sync(0xffffffffu, v, 16); \
    v += __shfl_xor_sync(0xffffffffu, v, 8);  \
    v += __shfl_xor_sync(0xffffffffu, v, 4);  \
    v += __shfl_xor_sync(0xffffffffu, v, 2);  \
    v += __shfl_xor_sync(0xffffffffu, v, 1);  \
} while (0)

// Load W2[k][pair] = w[d][k]^2 for d = 4*tid..4*tid+3
static __device__ __forceinline__ void load_w2(const float4* __restrict__ w4,
                                               int tid, u64 W2p[4][2]) {
    float4 wq[4];
#pragma unroll
    for (int j = 0; j < 4; j++) wq[j] = __ldg(&w4[4 * tid + j]);
    const float wkj[4][4] = {
        {wq[0].x, wq[1].x, wq[2].x, wq[3].x},
        {wq[0].y, wq[1].y, wq[2].y, wq[3].y},
        {wq[0].z, wq[1].z, wq[2].z, wq[3].z},
        {wq[0].w, wq[1].w, wq[2].w, wq[3].w}};
#pragma unroll
    for (int k = 0; k < 4; k++) {
        W2p[k][0] = pk2(wkj[k][0] * wkj[k][0], wkj[k][1] * wkj[k][1]);
        W2p[k][1] = pk2(wkj[k][2] * wkj[k][2], wkj[k][3] * wkj[k][3]);
    }
}

// ============================ K1: per-warp partials ============================
__global__ __launch_bounds__(NT, 2)
void k_partials(const float4* __restrict__ x4, const float4* __restrict__ w4)
{
    const int tid  = threadIdx.x;
    const int lane = tid & 31;
    const int wid  = tid >> 5;
    const int s0   = blockIdx.x * TR1;
    const int b    = blockIdx.y;

    const long base = ((long)b * SEQ) * D4 + tid;

    u64 W2p[4][2];
    load_w2(w4, tid, W2p);

    // window: rows s0 .. s0-5
    u64 Xp[6][2];
#pragma unroll
    for (int j = 0; j <= 5; j++) {
        const int s  = s0 - j;
        const int sl = SLOT6(-j);
        if (s >= 0) {
            const float4 v = x4[base + (long)s * D4];
            Xp[sl][0] = pk2(v.x, v.y); Xp[sl][1] = pk2(v.z, v.w);
        } else {
            Xp[sl][0] = 0ull; Xp[sl][1] = 0ull;
        }
    }

#pragma unroll
    for (int t = 0; t < TR1; t++) {
        if (t > 0) {
            const float4 v = x4[base + (long)(s0 + t) * D4];
            const int sl = SLOT6(t);
            Xp[sl][0] = pk2(v.x, v.y); Xp[sl][1] = pk2(v.z, v.w);
        }
        const int a0 = SLOT6(t),     a1 = SLOT6(t - 1), a2 = SLOT6(t - 2);
        const int a3 = SLOT6(t - 3), a4 = SLOT6(t - 4), a5 = SLOT6(t - 5);

        u64 vd0 = 0ull, vd1 = 0ull, vd2 = 0ull;
        u64 vv0 = 0ull, vv1 = 0ull, vv2 = 0ull, vv3 = 0ull;
#pragma unroll
        for (int p = 0; p < 2; p++) {
            const u64 x0 = Xp[a0][p], x1 = Xp[a1][p], x2 = Xp[a2][p];
            const u64 x3 = Xp[a3][p], x4v = Xp[a4][p], x5 = Xp[a5][p];
            vd0 = fma2(x0, x1, vd0);
            vd1 = fma2(x0, x2, vd1);
            vd2 = fma2(x0, x3, vd2);
            const u64 q0 = mul2(x0, x2);
            const u64 q1 = mul2(x1, x3);
            const u64 q2 = mul2(x2, x4v);
            const u64 q3 = mul2(x3, x5);
            vv0 = fma2(mul2(q0, q0), W2p[0][p], vv0);
            vv1 = fma2(mul2(q1, q1), W2p[1][p], vv1);
            vv2 = fma2(mul2(q2, q2), W2p[2][p], vv2);
            vv3 = fma2(mul2(q3, q3), W2p[3][p], vv3);
        }
        float v0, v1, v2, v3, v4, v5, v6;
        {
            float lo, hi;
            up2(vd0, lo, hi); v0 = lo + hi;
            up2(vd1, lo, hi); v1 = lo + hi;
            up2(vd2, lo, hi); v2 = lo + hi;
            up2(vv0, lo, hi); v3 = lo + hi;
            up2(vv1, lo, hi); v4 = lo + hi;
            up2(vv2, lo, hi); v5 = lo + hi;
            up2(vv3, lo, hi); v6 = lo + hi;
        }
        WSUM(v0); WSUM(v1); WSUM(v2); WSUM(v3); WSUM(v4); WSUM(v5); WSUM(v6);

        float ov = v0;
        ov = (lane == 1) ? v1 : ov;
        ov = (lane == 2) ? v2 : ov;
        ov = (lane == 3) ? v3 : ov;
        ov = (lane == 4) ? v4 : ov;
        ov = (lane == 5) ? v5 : ov;
        ov = (lane == 6) ? v6 : ov;
        if (lane < 7) g_part[b][s0 + t][lane][wid] = ov;
    }
}

// ============================ K2: scales per row ============================
__global__ void k_scales(const float* __restrict__ alpha)
{
    const int idx = blockIdx.x * blockDim.x + threadIdx.x;   // 0..B*SEQ-1
    const int b = idx >> 11;         // SEQ = 2048
    const int s = idx & (SEQ - 1);

    float sums[7];
#pragma unroll
    for (int v = 0; v < 7; v++) {
        const float4* p = (const float4*)&g_part[b][s][v][0];
        float4 a = p[0], c = p[1], d = p[2], e = p[3];
        sums[v] = ((a.x + a.y) + (a.z + a.w)) + ((c.x + c.y) + (c.z + c.w))
                + ((d.x + d.y) + (d.z + d.w)) + ((e.x + e.y) + (e.z + e.w));
    }
    const float invD = 1.0f / (float)DIM;
    float4 cs;
    cs.x = rsqrtf(sums[3] * invD + EPSV);
    cs.y = tanhf(sums[0] * __ldg(&alpha[0])) * rsqrtf(sums[4] * invD + EPSV);
    cs.z = tanhf(sums[1] * __ldg(&alpha[1])) * rsqrtf(sums[5] * invD + EPSV);
    cs.w = tanhf(sums[2] * __ldg(&alpha[2])) * rsqrtf(sums[6] * invD + EPSV);
    g_scale[b][s] = cs;
}

// ============================ K3: streaming recombine ============================
__global__ __launch_bounds__(NT, 2)
void k_combine(const float4* __restrict__ x4, const float4* __restrict__ w4,
               const float4* __restrict__ rmsw4, float4* __restrict__ out4)
{
    const int tid = threadIdx.x;
    const int s0  = blockIdx.x * TR3;
    const int b   = blockIdx.y;

    const long base = ((long)b * SEQ) * D4 + tid;

    u64 W2p[4][2];
    load_w2(w4, tid, W2p);
    const float4 rq = __ldg(&rmsw4[tid]);
    const u64 rp[2] = {pk2(rq.x, rq.y), pk2(rq.z, rq.w)};

    u64 Xp[6][2];
#pragma unroll
    for (int j = 0; j <= 5; j++) {
        const int s  = s0 - j;
        const int sl = SLOT6(-j);
        if (s >= 0) {
            const float4 v = x4[base + (long)s * D4];
            Xp[sl][0] = pk2(v.x, v.y); Xp[sl][1] = pk2(v.z, v.w);
        } else {
            Xp[sl][0] = 0ull; Xp[sl][1] = 0ull;
        }
    }

#pragma unroll
    for (int t = 0; t < TR3; t++) {
        if (t > 0) {
            const float4 v = x4[base + (long)(s0 + t) * D4];
            const int sl = SLOT6(t);
            Xp[sl][0] = pk2(v.x, v.y); Xp[sl][1] = pk2(v.z, v.w);
        }
        const float4 cs = g_scale[b][s0 + t];
        const u64 cp0 = pk2(cs.x, cs.x), cp1 = pk2(cs.y, cs.y);
        const u64 cp2 = pk2(cs.z, cs.z), cp3 = pk2(cs.w, cs.w);

        const int a0 = SLOT6(t),     a1 = SLOT6(t - 1), a2 = SLOT6(t - 2);
        const int a3 = SLOT6(t - 3), a4 = SLOT6(t - 4), a5 = SLOT6(t - 5);

        float oo[4];
#pragma unroll
        for (int p = 0; p < 2; p++) {
            const u64 x0 = Xp[a0][p];
            const u64 q0 = mul2(x0, Xp[a2][p]);
            const u64 q1 = mul2(Xp[a1][p], Xp[a3][p]);
            const u64 q2 = mul2(Xp[a2][p], Xp[a4][p]);
            const u64 q3 = mul2(Xp[a3][p], Xp[a5][p]);
            u64 acc = mul2(cp0, mul2(q0, W2p[0][p]));
            acc = fma2(cp1, mul2(q1, W2p[1][p]), acc);
            acc = fma2(cp2, mul2(q2, W2p[2][p]), acc);
            acc = fma2(cp3, mul2(q3, W2p[3][p]), acc);
            const u64 o = fma2(rp[p], acc, x0);
            up2(o, oo[2 * p], oo[2 * p + 1]);
        }
        float4 ov; ov.x = oo[0]; ov.y = oo[1]; ov.z = oo[2]; ov.w = oo[3];
        out4[base + (long)(s0 + t) * D4] = ov;
    }
}

extern "C" void kernel_launch(void* const* d_in, const int* in_sizes, int n_in,
                              void* d_out, int out_size)
{
    const float* x     = (const float*)d_in[0];
    const float* w     = (const float*)d_in[1];
    const float* alpha = (const float*)d_in[2];
    const float* rmsw  = (const float*)d_in[3];
    float* out = (float*)d_out;

    const long total = (long)in_sizes[0];
    const int  B     = (int)(total / ((long)SEQ * DIM));   // = 2

    dim3 g1(SEQ / TR1, B);
    k_partials<<<g1, NT>>>((const float4*)x, (const float4*)w);

    k_scales<<<(B * SEQ) / 256, 256>>>(alpha);

    dim3 g3(SEQ / TR3, B);
    k_combine<<<g3, NT>>>((const float4*)x, (const float4*)w,
                          (const float4*)rmsw, (float4*)out);
}